// round 9
// baseline (speedup 1.0000x reference)
#include <cuda_runtime.h>
#include <math.h>
#include <stdint.h>

#define B 64
#define T 1024
#define E 512
#define R 1024
#define A 128
#define F 32
#define KS 31
#define PADC 15

#define TM 128          // t-tile of energy GEMM
#define KC 32           // k-chunk
#define NCHUNK 17       // 16 key chunks + 1 feat/Wloc chunk
#define SAP 40          // A smem row stride (floats), k-pair layout, conflict-free
#define SBP 40          // B smem col stride (floats)
#define SZA (TM * SAP)  // 5120 floats per A stage
#define SZB (A * SBP)   // 5120 floats per B stage
#define SMEM_BYTES ((2 * SZA + 2 * SZB) * 4)   // 81920 B

// prep grid layout
#define NB_LOC  256
#define NB_QP   64
#define NB_WB   68
#define NB_PREP (NB_LOC + NB_QP + NB_WB + 1)

// scratch (allocation-free rule: __device__ globals)
__device__ float  g_q[B * A];
__device__ float4 g_feat4[(size_t)B * T * F / 4];     // [B][T][F]
__device__ float  g_e[B * T];
__device__ float4 g_ctxpart4[B * 16 * E / 4];
__device__ float  g_wbT[(E + F) * A];                 // per-chunk [col][k-pair-permuted]
__device__ int    g_maskmode;
__device__ int    g_cnt[B];                           // ctx ticket counters

// ---------------------------------------------------------------------------
__device__ __forceinline__ void cp16(float* dst_smem, const float* src) {
    uint32_t d = (uint32_t)__cvta_generic_to_shared(dst_smem);
    asm volatile("cp.async.ca.shared.global [%0], [%1], 16;" :: "r"(d), "l"(src));
}
__device__ __forceinline__ float cvt_tf32(float x) {
    uint32_t u;
    asm("cvt.rna.tf32.f32 %0, %1;" : "=r"(u) : "f"(x));
    return __uint_as_float(u);
}
__device__ __forceinline__ void mma_tf32(float& c0, float& c1, float& c2, float& c3,
                                         uint32_t a0, uint32_t a1, uint32_t a2, uint32_t a3,
                                         uint32_t b0, uint32_t b1) {
    asm volatile(
        "mma.sync.aligned.m16n8k8.row.col.f32.tf32.tf32.f32 "
        "{%0,%1,%2,%3}, {%4,%5,%6,%7}, {%8,%9}, {%0,%1,%2,%3};"
        : "+f"(c0), "+f"(c1), "+f"(c2), "+f"(c3)
        : "r"(a0), "r"(a1), "r"(a2), "r"(a3), "r"(b0), "r"(b1));
}
__device__ __forceinline__ bool read_mask(const void* m, int idx, int mode) {
    if (mode == 1) return ((const int*)m)[idx] != 0;
    if (mode == 2) return ((const float*)m)[idx] != 0.f;
    return ((const unsigned char*)m)[idx] != 0;
}

// ---------------------------------------------------------------------------
// PREP: fused loc-conv / qproj / wbT / mask-sniff+counter-reset
// ---------------------------------------------------------------------------
__global__ void __launch_bounds__(256)
prep_kernel(const float* __restrict__ query,
            const float* __restrict__ Wq,
            const float* __restrict__ cat,
            const float* __restrict__ conv_w,
            const float* __restrict__ gamma,
            const float* __restrict__ beta,
            const float* __restrict__ mean,
            const float* __restrict__ var,
            const float* __restrict__ Wk,
            const float* __restrict__ Wloc,
            const unsigned int* __restrict__ maskw) {
    int blk = blockIdx.x;
    int tid = threadIdx.x;

    if (blk < NB_LOC) {
        // ---------------- loc: conv1d -> relu -> BN -> g_feat ----------------
        int b  = blk >> 2;
        int t0 = (blk & 3) * 256;

        __shared__ float xs[2][288];
        __shared__ float cwT[2 * KS * F];
        __shared__ float bnS[F], bnB[F];

        for (int idx = tid; idx < 2 * 286; idx += 256) {
            int ch = idx / 286, p = idx % 286;
            int tt = t0 - PADC + p;
            xs[ch][p] = (tt >= 0 && tt < T)
                      ? cat[(size_t)b * 2 * T + (size_t)ch * T + tt] : 0.f;
        }
        for (int idx = tid; idx < 2 * KS * F; idx += 256) {
            int f = idx & 31;
            int rest = idx >> 5;
            int ch = rest / KS, k = rest % KS;
            cwT[idx] = conv_w[(f * 2 + ch) * KS + k];
        }
        if (tid < F) {
            float s = rsqrtf(var[tid] + 1e-5f) * gamma[tid];
            bnS[tid] = s;
            bnB[tid] = beta[tid] - mean[tid] * s;
        }
        __syncthreads();

        float4 acc[8];
        #pragma unroll
        for (int u = 0; u < 8; u++) acc[u] = make_float4(0.f, 0.f, 0.f, 0.f);

        #pragma unroll 1
        for (int ch = 0; ch < 2; ch++) {
            #pragma unroll 1
            for (int k = 0; k < KS; k++) {
                float xv = xs[ch][tid + k];
                const float4* c4 = (const float4*)(cwT + (ch * KS + k) * F);
                #pragma unroll
                for (int u = 0; u < 8; u++) {
                    float4 c = c4[u];
                    acc[u].x += xv * c.x; acc[u].y += xv * c.y;
                    acc[u].z += xv * c.z; acc[u].w += xv * c.w;
                }
            }
        }

        size_t base = ((size_t)b * T + t0 + tid) * (F / 4);
        #pragma unroll
        for (int u = 0; u < 8; u++) {
            int f0 = u * 4;
            float4 o;
            o.x = cvt_tf32(fmaxf(acc[u].x, 0.f) * bnS[f0 + 0] + bnB[f0 + 0]);
            o.y = cvt_tf32(fmaxf(acc[u].y, 0.f) * bnS[f0 + 1] + bnB[f0 + 1]);
            o.z = cvt_tf32(fmaxf(acc[u].z, 0.f) * bnS[f0 + 2] + bnB[f0 + 2]);
            o.w = cvt_tf32(fmaxf(acc[u].w, 0.f) * bnS[f0 + 3] + bnB[f0 + 3]);
            g_feat4[base + u] = o;
        }
    } else if (blk < NB_LOC + NB_QP) {
        // ---------------- qproj ----------------
        int b = blk - NB_LOC;
        int g = tid >> 7, a = tid & 127;
        __shared__ float sred[2][128];
        const float* qb = query + (size_t)b * R + g * 512;
        const float* wp = Wq + (size_t)(g * 512) * A + a;
        float acc = 0.f;
        #pragma unroll 8
        for (int r = 0; r < 512; r++)
            acc += qb[r] * wp[(size_t)r * A];
        sred[g][a] = acc;
        __syncthreads();
        if (g == 0)
            g_q[b * A + a] = sred[0][a] + sred[1][a];
    } else if (blk < NB_LOC + NB_QP + NB_WB) {
        // -------- wbT: tf32-round Wk++Wloc, transpose+pair-permute per chunk --------
        int base = (blk - NB_LOC - NB_QP) * 1024;
        #pragma unroll
        for (int i = 0; i < 4; i++) {
            int idx = base + i * 256 + tid;          // source linear [kg][a]
            int kg = idx >> 7, a = idx & 127;
            float x = (idx < E * A) ? Wk[idx] : Wloc[idx - E * A];
            int ch = kg >> 5, kl = kg & 31;
            int ks2 = kl >> 3, j = kl & 3, half = (kl >> 2) & 1;
            g_wbT[ch * (KC * A) + a * KC + ks2 * 8 + j * 2 + half] = cvt_tf32(x);
        }
    } else {
        // ---------------- mask sniff + counter reset ----------------
        __shared__ int s_not_int, s_not_flt;
        if (tid == 0) { s_not_int = 0; s_not_flt = 0; }
        if (tid < B) g_cnt[tid] = 0;
        __syncthreads();
        int not_int = 0, not_flt = 0;
        for (int i = tid; i < (B * T) / 4; i += 256) {
            unsigned int x = maskw[i];
            if (x > 1u) not_int = 1;
            if (x != 0u && x != 0x3F800000u) not_flt = 1;
        }
        if (not_int) atomicOr(&s_not_int, 1);
        if (not_flt) atomicOr(&s_not_flt, 1);
        __syncthreads();
        if (tid == 0)
            g_maskmode = (!s_not_int) ? 1 : ((!s_not_flt) ? 2 : 0);
    }
}

// ---------------------------------------------------------------------------
// energy: tf32 MMA 128x128x(512+32); A dbl-buffered smem (k-pair layout),
// B cp.async dbl-buffered from pre-permuted g_wbT; one barrier per chunk.
// ---------------------------------------------------------------------------
__global__ void __launch_bounds__(256, 2)
energy_kernel(const float* __restrict__ key,
              const void* __restrict__ mask,
              const float* __restrict__ v) {
    int b  = blockIdx.y;
    int t0 = blockIdx.x * TM;
    int tid = threadIdx.x;
    int lane = tid & 31;
    int wid  = tid >> 5;
    int warp_m = wid >> 2;
    int warp_n = wid & 3;

    extern __shared__ float dsm[];
    float* stA[2] = {dsm, dsm + SZA};
    float* stB[2] = {dsm + 2 * SZA, dsm + 2 * SZA + SZB};

    float acc[4][4][4];
    #pragma unroll
    for (int i = 0; i < 4; i++)
        #pragma unroll
        for (int j = 0; j < 4; j++)
            #pragma unroll
            for (int r = 0; r < 4; r++) acc[i][j][r] = 0.f;

    const float* keyb  = key + (size_t)b * T * E + (size_t)t0 * E;
    const float* featb = (const float*)g_feat4 + ((size_t)b * T + t0) * F;

    // per-thread A indices: 4 float4s, row = li>>3, col-group c = li&7 (k=4c..4c+3)
    int rowA[4], cA[4], sbase[4];
    #pragma unroll
    for (int i = 0; i < 4; i++) {
        int li = tid + i * 256;
        rowA[i] = li >> 3;
        cA[i]   = li & 7;
        sbase[i] = rowA[i] * SAP + (cA[i] >> 1) * 8 + (cA[i] & 1);
    }

    // ---- prologue: chunk 0 ----
    float4 aPre[4];
    #pragma unroll
    for (int i = 0; i < 4; i++)
        aPre[i] = *(const float4*)(keyb + (size_t)rowA[i] * E + cA[i] * 4);
    #pragma unroll
    for (int i = 0; i < 4; i++) {
        int li = tid + i * 256;
        int col = li >> 3, og = (li & 7) * 4;
        cp16(stB[0] + col * SBP + og, g_wbT + col * KC + og);
    }
    asm volatile("cp.async.commit_group;");
    #pragma unroll
    for (int i = 0; i < 4; i++) {
        float* d = stA[0] + sbase[i];
        d[0] = cvt_tf32(aPre[i].x); d[2] = cvt_tf32(aPre[i].y);
        d[4] = cvt_tf32(aPre[i].z); d[6] = cvt_tf32(aPre[i].w);
    }
    asm volatile("cp.async.wait_group 0;");
    __syncthreads();

    for (int c = 0; c < NCHUNK; c++) {
        float* sA = stA[c & 1];
        float* sB = stB[c & 1];
        bool has_next = (c + 1 < NCHUNK);

        if (has_next) {
            if (c + 1 < 16) {
                int e0 = (c + 1) * KC;
                #pragma unroll
                for (int i = 0; i < 4; i++)
                    aPre[i] = *(const float4*)(keyb + (size_t)rowA[i] * E + e0 + cA[i] * 4);
            } else {
                #pragma unroll
                for (int i = 0; i < 4; i++)
                    aPre[i] = *(const float4*)(featb + (size_t)rowA[i] * F + cA[i] * 4);
            }
            const float* wsrc = g_wbT + (size_t)(c + 1) * (KC * A);
            float* sBn = stB[(c + 1) & 1];
            #pragma unroll
            for (int i = 0; i < 4; i++) {
                int li = tid + i * 256;
                int col = li >> 3, og = (li & 7) * 4;
                cp16(sBn + col * SBP + og, wsrc + col * KC + og);
            }
            asm volatile("cp.async.commit_group;");
        }

        // ---- 4 k-steps, LDS.64 fragment loads ----
        #pragma unroll
        for (int ks = 0; ks < 4; ks++) {
            uint32_t af[4][4];
            #pragma unroll
            for (int mf = 0; mf < 4; mf++) {
                int r0 = warp_m * 64 + mf * 16 + (lane >> 2);
                float2 pa = *(float2*)(sA + r0 * SAP + ks * 8 + (lane & 3) * 2);
                float2 pb = *(float2*)(sA + (r0 + 8) * SAP + ks * 8 + (lane & 3) * 2);
                af[mf][0] = __float_as_uint(pa.x);
                af[mf][1] = __float_as_uint(pb.x);
                af[mf][2] = __float_as_uint(pa.y);
                af[mf][3] = __float_as_uint(pb.y);
            }
            uint32_t bf[4][2];
            #pragma unroll
            for (int nf = 0; nf < 4; nf++) {
                int col = warp_n * 32 + nf * 8 + (lane >> 2);
                float2 pb = *(float2*)(sB + col * SBP + ks * 8 + (lane & 3) * 2);
                bf[nf][0] = __float_as_uint(pb.x);
                bf[nf][1] = __float_as_uint(pb.y);
            }
            #pragma unroll
            for (int mf = 0; mf < 4; mf++)
                #pragma unroll
                for (int nf = 0; nf < 4; nf++)
                    mma_tf32(acc[mf][nf][0], acc[mf][nf][1],
                             acc[mf][nf][2], acc[mf][nf][3],
                             af[mf][0], af[mf][1], af[mf][2], af[mf][3],
                             bf[nf][0], bf[nf][1]);
        }

        if (has_next) {
            float* dA = stA[(c + 1) & 1];
            #pragma unroll
            for (int i = 0; i < 4; i++) {
                float* d = dA + sbase[i];
                d[0] = cvt_tf32(aPre[i].x); d[2] = cvt_tf32(aPre[i].y);
                d[4] = cvt_tf32(aPre[i].z); d[6] = cvt_tf32(aPre[i].w);
            }
            asm volatile("cp.async.wait_group 0;");
            __syncthreads();
        }
    }

    // ---- epilogue: e[t] = sum_a v[a] * tanh(q[a] + S[t,a]) ----
    float part[4][2];
    #pragma unroll
    for (int mf = 0; mf < 4; mf++) { part[mf][0] = 0.f; part[mf][1] = 0.f; }

    #pragma unroll
    for (int nf = 0; nf < 4; nf++) {
        int c0 = warp_n * 32 + nf * 8 + 2 * (lane & 3);
        float qv0 = g_q[b * A + c0],     qv1 = g_q[b * A + c0 + 1];
        float vv0 = v[c0],               vv1 = v[c0 + 1];
        #pragma unroll
        for (int mf = 0; mf < 4; mf++) {
            part[mf][0] += vv0 * tanhf(qv0 + acc[mf][nf][0])
                         + vv1 * tanhf(qv1 + acc[mf][nf][1]);
            part[mf][1] += vv0 * tanhf(qv0 + acc[mf][nf][2])
                         + vv1 * tanhf(qv1 + acc[mf][nf][3]);
        }
    }

    __syncthreads();
    float* red = dsm;                // reuse: [128][5]
    #pragma unroll
    for (int mf = 0; mf < 4; mf++) {
        #pragma unroll
        for (int r = 0; r < 2; r++) {
            float p = part[mf][r];
            p += __shfl_xor_sync(0xFFFFFFFFu, p, 1);
            p += __shfl_xor_sync(0xFFFFFFFFu, p, 2);
            if ((lane & 3) == 0) {
                int row = warp_m * 64 + mf * 16 + (lane >> 2) + r * 8;
                red[row * 5 + warp_n] = p;
            }
        }
    }
    __syncthreads();

    if (tid < TM) {
        float s = red[tid * 5 + 0] + red[tid * 5 + 1]
                + red[tid * 5 + 2] + red[tid * 5 + 3];
        int t = t0 + tid;
        int mode = g_maskmode;
        g_e[b * T + t] = read_mask(mask, b * T + t, mode) ? -INFINITY : s;
    }
}

// ---------------------------------------------------------------------------
// ctx: inline softmax + context partial + last-block final reduce (ticketed)
// ---------------------------------------------------------------------------
__global__ void __launch_bounds__(256)
ctx_kernel(const float* __restrict__ key,
           float* __restrict__ out) {
    int b = blockIdx.y;
    int c = blockIdx.x;             // 0..15, 64 t each
    int tid = threadIdx.x;          // 256
    int e4 = tid & 127, h = tid >> 7;

    __shared__ float sred[256];
    __shared__ float ws[64];
    __shared__ int s_last;

    // ---- softmax normalization over full T ----
    float vals[4];
    float m = -INFINITY;
    #pragma unroll
    for (int i = 0; i < 4; i++) {
        vals[i] = g_e[b * T + tid + i * 256];
        m = fmaxf(m, vals[i]);
    }
    sred[tid] = m; __syncthreads();
    for (int s = 128; s > 0; s >>= 1) {
        if (tid < s) sred[tid] = fmaxf(sred[tid], sred[tid + s]);
        __syncthreads();
    }
    m = sred[0]; __syncthreads();

    float sum = 0.f;
    #pragma unroll
    for (int i = 0; i < 4; i++)
        sum += expf(vals[i] - m);
    sred[tid] = sum; __syncthreads();
    for (int s = 128; s > 0; s >>= 1) {
        if (tid < s) sred[tid] += sred[tid + s];
        __syncthreads();
    }
    float inv = 1.f / sred[0];
    __syncthreads();

    // ---- this block's 64-t weight slice ----
    if (tid < 64) {
        float w = expf(g_e[b * T + c * 64 + tid] - m) * inv;
        ws[tid] = w;
        out[B * E + (size_t)b * T + c * 64 + tid] = w;
    }
    __syncthreads();

    // ---- context partial ----
    const float* w = ws + h * 32;
    const float4* kp = (const float4*)(key + (size_t)b * T * E)
                     + (size_t)(c * 64 + h * 32) * (E / 4) + e4;
    float4 acc = make_float4(0.f, 0.f, 0.f, 0.f);
    #pragma unroll 8
    for (int t = 0; t < 32; t++) {
        float4 k4 = kp[(size_t)t * (E / 4)];
        float wt = w[t];
        acc.x += wt * k4.x; acc.y += wt * k4.y;
        acc.z += wt * k4.z; acc.w += wt * k4.w;
    }
    __shared__ float4 sred4[256];
    sred4[tid] = acc;
    __syncthreads();
    if (h == 0) {
        float4 o = sred4[tid];
        float4 p = sred4[tid + 128];
        o.x += p.x; o.y += p.y; o.z += p.z; o.w += p.w;
        g_ctxpart4[(b * 16 + c) * (E / 4) + e4] = o;
    }
    __threadfence();
    __syncthreads();

    // ---- ticket: last block of this b does the final reduce ----
    if (tid == 0)
        s_last = (atomicAdd(&g_cnt[b], 1) == 15);
    __syncthreads();
    if (s_last) {
        const float* parts = (const float*)g_ctxpart4;
        #pragma unroll 1
        for (int e = tid; e < E; e += 256) {
            float s = 0.f;
            #pragma unroll
            for (int k = 0; k < 16; k++)
                s += parts[(b * 16 + k) * E + e];
            out[(size_t)b * E + e] = s;
        }
    }
}

// ---------------------------------------------------------------------------
extern "C" void kernel_launch(void* const* d_in, const int* in_sizes, int n_in,
                              void* d_out, int out_size) {
    const float* query  = (const float*)d_in[0];
    const float* key    = (const float*)d_in[1];
    const float* cat    = (const float*)d_in[2];
    const void*  mask   = (const void*)d_in[3];
    const float* Wq     = (const float*)d_in[4];
    const float* Wk     = (const float*)d_in[5];
    const float* conv_w = (const float*)d_in[6];
    const float* gamma  = (const float*)d_in[7];
    const float* beta   = (const float*)d_in[8];
    const float* mean   = (const float*)d_in[9];
    const float* var    = (const float*)d_in[10];
    const float* Wloc   = (const float*)d_in[11];
    const float* v      = (const float*)d_in[12];
    float* out = (float*)d_out;

    cudaFuncSetAttribute(energy_kernel,
                         cudaFuncAttributeMaxDynamicSharedMemorySize, SMEM_BYTES);

    prep_kernel<<<NB_PREP, 256>>>(query, Wq, cat, conv_w, gamma, beta, mean, var,
                                  Wk, Wloc, (const unsigned int*)mask);
    energy_kernel<<<dim3(T / TM, B), 256, SMEM_BYTES>>>(key, mask, v);
    ctx_kernel<<<dim3(16, B), 256>>>(key, out);
}

// round 10
// speedup vs baseline: 1.0574x; 1.0574x over previous
#include <cuda_runtime.h>
#include <math.h>
#include <stdint.h>

#define B 64
#define T 1024
#define E 512
#define R 1024
#define A 128
#define F 32
#define KS 31
#define PADC 15

#define TM 128          // t-tile of energy GEMM
#define KC 32           // k-chunk
#define NCHUNK 17       // 16 key chunks + 1 feat/Wloc chunk
#define SA 36           // sA stride (conflict-free A frags)
#define SB 136          // sB stride (conflict-free B frags)
#define SZA (TM * SA)   // 4608 floats
#define SZB (KC * SB)   // 4352 floats
#define SMEM_BYTES ((SZA + 2 * SZB) * 4)   // 53248 B

// prep grid layout
#define NB_LOC  512     // 8 per batch x 64 (128 t each, f split 2-way)
#define NB_QP   64
#define NB_WB   68
#define NB_PREP (NB_LOC + NB_QP + NB_WB + 1)

// scratch (allocation-free rule: __device__ globals)
__device__ float  g_q[B * A];
__device__ float4 g_feat4[(size_t)B * T * F / 4];     // [B][T][F]
__device__ float  g_e[B * T];
__device__ float4 g_ctxpart4[B * 16 * E / 4];
__device__ float  g_wb[(E + F) * A];                  // tf32-rounded Wk;Wloc
__device__ int    g_maskmode;
__device__ int    g_cnt[B];                           // ctx ticket counters

// ---------------------------------------------------------------------------
__device__ __forceinline__ void cp16(float* dst_smem, const float* src) {
    uint32_t d = (uint32_t)__cvta_generic_to_shared(dst_smem);
    asm volatile("cp.async.ca.shared.global [%0], [%1], 16;" :: "r"(d), "l"(src));
}
__device__ __forceinline__ float cvt_tf32(float x) {
    uint32_t u;
    asm("cvt.rna.tf32.f32 %0, %1;" : "=r"(u) : "f"(x));
    return __uint_as_float(u);
}
__device__ __forceinline__ void mma_tf32(float& c0, float& c1, float& c2, float& c3,
                                         uint32_t a0, uint32_t a1, uint32_t a2, uint32_t a3,
                                         uint32_t b0, uint32_t b1) {
    asm volatile(
        "mma.sync.aligned.m16n8k8.row.col.f32.tf32.tf32.f32 "
        "{%0,%1,%2,%3}, {%4,%5,%6,%7}, {%8,%9}, {%0,%1,%2,%3};"
        : "+f"(c0), "+f"(c1), "+f"(c2), "+f"(c3)
        : "r"(a0), "r"(a1), "r"(a2), "r"(a3), "r"(b0), "r"(b1));
}
__device__ __forceinline__ bool read_mask(const void* m, int idx, int mode) {
    if (mode == 1) return ((const int*)m)[idx] != 0;
    if (mode == 2) return ((const float*)m)[idx] != 0.f;
    return ((const unsigned char*)m)[idx] != 0;
}

// ---------------------------------------------------------------------------
// PREP: fused loc-conv / qproj / wb / mask-sniff+counter-reset
// ---------------------------------------------------------------------------
__global__ void __launch_bounds__(256)
prep_kernel(const float* __restrict__ query,
            const float* __restrict__ Wq,
            const float* __restrict__ cat,
            const float* __restrict__ conv_w,
            const float* __restrict__ gamma,
            const float* __restrict__ beta,
            const float* __restrict__ mean,
            const float* __restrict__ var,
            const float* __restrict__ Wk,
            const float* __restrict__ Wloc,
            const unsigned int* __restrict__ maskw) {
    int blk = blockIdx.x;
    int tid = threadIdx.x;

    if (blk < NB_LOC) {
        // ------- loc: conv1d -> relu -> BN -> g_feat; 128 t x 2 f-halves -------
        int b  = blk >> 3;
        int t0 = (blk & 7) * 128;
        int t  = tid & 127, fh = tid >> 7;      // fh selects features 16*fh..16*fh+15

        __shared__ float xs[2][160];            // 128 + 30 halo (+2 pad)
        __shared__ float cwT[2 * KS * F];       // [ch][k][f] (f contiguous)
        __shared__ float bnS[F], bnB[F];

        for (int idx = tid; idx < 2 * 158; idx += 256) {
            int ch = idx / 158, p = idx % 158;
            int tt = t0 - PADC + p;
            xs[ch][p] = (tt >= 0 && tt < T)
                      ? cat[(size_t)b * 2 * T + (size_t)ch * T + tt] : 0.f;
        }
        for (int idx = tid; idx < 2 * KS * F; idx += 256) {
            int f = idx & 31;
            int rest = idx >> 5;                 // ch*31 + k
            int ch = rest / KS, k = rest % KS;
            cwT[idx] = conv_w[(f * 2 + ch) * KS + k];
        }
        if (tid < F) {
            float s = rsqrtf(var[tid] + 1e-5f) * gamma[tid];
            bnS[tid] = s;
            bnB[tid] = beta[tid] - mean[tid] * s;
        }
        __syncthreads();

        float4 acc[4];
        #pragma unroll
        for (int u = 0; u < 4; u++) acc[u] = make_float4(0.f, 0.f, 0.f, 0.f);

        #pragma unroll
        for (int ch = 0; ch < 2; ch++) {
            #pragma unroll
            for (int k = 0; k < KS; k++) {
                float xv = xs[ch][t + k];
                const float4* c4 = (const float4*)(cwT + (ch * KS + k) * F) + fh * 4;
                #pragma unroll
                for (int u = 0; u < 4; u++) {
                    float4 c = c4[u];
                    acc[u].x += xv * c.x; acc[u].y += xv * c.y;
                    acc[u].z += xv * c.z; acc[u].w += xv * c.w;
                }
            }
        }

        size_t base = ((size_t)b * T + t0 + t) * (F / 4) + fh * 4;
        #pragma unroll
        for (int u = 0; u < 4; u++) {
            int f0 = fh * 16 + u * 4;
            float4 o;
            o.x = cvt_tf32(fmaxf(acc[u].x, 0.f) * bnS[f0 + 0] + bnB[f0 + 0]);
            o.y = cvt_tf32(fmaxf(acc[u].y, 0.f) * bnS[f0 + 1] + bnB[f0 + 1]);
            o.z = cvt_tf32(fmaxf(acc[u].z, 0.f) * bnS[f0 + 2] + bnB[f0 + 2]);
            o.w = cvt_tf32(fmaxf(acc[u].w, 0.f) * bnS[f0 + 3] + bnB[f0 + 3]);
            g_feat4[base + u] = o;
        }
    } else if (blk < NB_LOC + NB_QP) {
        // ---------------- qproj ----------------
        int b = blk - NB_LOC;
        int g = tid >> 7, a = tid & 127;
        __shared__ float sred[2][128];
        const float* qb = query + (size_t)b * R + g * 512;
        const float* wp = Wq + (size_t)(g * 512) * A + a;
        float acc = 0.f;
        #pragma unroll 8
        for (int r = 0; r < 512; r++)
            acc += qb[r] * wp[(size_t)r * A];
        sred[g][a] = acc;
        __syncthreads();
        if (g == 0)
            g_q[b * A + a] = sred[0][a] + sred[1][a];
    } else if (blk < NB_LOC + NB_QP + NB_WB) {
        // ---------------- wb: tf32-round Wk ++ Wloc (linear) ----------------
        int base = (blk - NB_LOC - NB_QP) * 1024;
        #pragma unroll
        for (int i = 0; i < 4; i++) {
            int idx = base + i * 256 + tid;
            float x = (idx < E * A) ? Wk[idx] : Wloc[idx - E * A];
            g_wb[idx] = cvt_tf32(x);
        }
    } else {
        // ---------------- mask sniff + counter reset ----------------
        __shared__ int s_not_int, s_not_flt;
        if (tid == 0) { s_not_int = 0; s_not_flt = 0; }
        if (tid < B) g_cnt[tid] = 0;
        __syncthreads();
        int not_int = 0, not_flt = 0;
        for (int i = tid; i < (B * T) / 4; i += 256) {
            unsigned int x = maskw[i];
            if (x > 1u) not_int = 1;
            if (x != 0u && x != 0x3F800000u) not_flt = 1;
        }
        if (not_int) atomicOr(&s_not_int, 1);
        if (not_flt) atomicOr(&s_not_flt, 1);
        __syncthreads();
        if (tid == 0)
            g_maskmode = (!s_not_int) ? 1 : ((!s_not_flt) ? 2 : 0);
    }
}

// ---------------------------------------------------------------------------
// energy: tf32 MMA GEMM 128x128x(512+32)  (R8 proven config)
//   A: register-prefetch, cvt at STS (float4), B: cp.async 2-stage
// ---------------------------------------------------------------------------
__global__ void __launch_bounds__(256, 2)
energy_kernel(const float* __restrict__ key,
              const void* __restrict__ mask,
              const float* __restrict__ v) {
    int b  = blockIdx.y;
    int t0 = blockIdx.x * TM;
    int tid = threadIdx.x;
    int lane = tid & 31;
    int wid  = tid >> 5;
    int warp_m = wid >> 2;
    int warp_n = wid & 3;

    extern __shared__ float dsm[];
    float* sA = dsm;                          // [128][36]
    float* stB[2] = {dsm + SZA, dsm + SZA + SZB};

    float acc[4][4][4];
    #pragma unroll
    for (int i = 0; i < 4; i++)
        #pragma unroll
        for (int j = 0; j < 4; j++)
            #pragma unroll
            for (int r = 0; r < 4; r++) acc[i][j][r] = 0.f;

    const float* keyb  = key + (size_t)b * T * E + (size_t)t0 * E;
    const float* featb = (const float*)g_feat4 + ((size_t)b * T + t0) * F;

    int rowA[4], cgA[4];
    #pragma unroll
    for (int i = 0; i < 4; i++) {
        int li = tid + i * 256;
        rowA[i] = li >> 3;
        cgA[i]  = (li & 7) * 4;
    }

    // ---- prologue: chunk 0 ----
    float4 aPre[4];
    #pragma unroll
    for (int i = 0; i < 4; i++)
        aPre[i] = *(const float4*)(keyb + (size_t)rowA[i] * E + cgA[i]);
    #pragma unroll
    for (int i = 0; i < 4; i++) {
        int li = tid + i * 256;
        int r = li >> 5, cg = li & 31;
        cp16(stB[0] + r * SB + cg * 4, g_wb + r * A + cg * 4);
    }
    asm volatile("cp.async.commit_group;");
    #pragma unroll
    for (int i = 0; i < 4; i++) {
        float4 t4 = make_float4(cvt_tf32(aPre[i].x), cvt_tf32(aPre[i].y),
                                cvt_tf32(aPre[i].z), cvt_tf32(aPre[i].w));
        *(float4*)(sA + rowA[i] * SA + cgA[i]) = t4;
    }
    asm volatile("cp.async.wait_group 0;");
    __syncthreads();

    for (int c = 0; c < NCHUNK; c++) {
        float* sB = stB[c & 1];
        bool has_next = (c + 1 < NCHUNK);
        if (has_next) {
            if (c + 1 < 16) {
                int e0 = (c + 1) * KC;
                #pragma unroll
                for (int i = 0; i < 4; i++)
                    aPre[i] = *(const float4*)(keyb + (size_t)rowA[i] * E + e0 + cgA[i]);
            } else {
                #pragma unroll
                for (int i = 0; i < 4; i++)
                    aPre[i] = *(const float4*)(featb + (size_t)rowA[i] * F + cgA[i]);
            }
            const float* wsrc = g_wb + (size_t)(c + 1) * KC * A;
            float* sBn = stB[(c + 1) & 1];
            #pragma unroll
            for (int i = 0; i < 4; i++) {
                int li = tid + i * 256;
                int r = li >> 5, cg = li & 31;
                cp16(sBn + r * SB + cg * 4, wsrc + r * A + cg * 4);
            }
            asm volatile("cp.async.commit_group;");
        }

        #pragma unroll
        for (int ks = 0; ks < 4; ks++) {
            int k0 = ks * 8;
            uint32_t af[4][4];
            #pragma unroll
            for (int mf = 0; mf < 4; mf++) {
                int rbase = warp_m * 64 + mf * 16 + (lane >> 2);
                int kcol = k0 + (lane & 3);
                af[mf][0] = __float_as_uint(sA[rbase * SA + kcol]);
                af[mf][1] = __float_as_uint(sA[(rbase + 8) * SA + kcol]);
                af[mf][2] = __float_as_uint(sA[rbase * SA + kcol + 4]);
                af[mf][3] = __float_as_uint(sA[(rbase + 8) * SA + kcol + 4]);
            }
            uint32_t bf[4][2];
            #pragma unroll
            for (int nf = 0; nf < 4; nf++) {
                int col = warp_n * 32 + nf * 8 + (lane >> 2);
                int krow = k0 + (lane & 3);
                bf[nf][0] = __float_as_uint(sB[krow * SB + col]);
                bf[nf][1] = __float_as_uint(sB[(krow + 4) * SB + col]);
            }
            #pragma unroll
            for (int mf = 0; mf < 4; mf++)
                #pragma unroll
                for (int nf = 0; nf < 4; nf++)
                    mma_tf32(acc[mf][nf][0], acc[mf][nf][1],
                             acc[mf][nf][2], acc[mf][nf][3],
                             af[mf][0], af[mf][1], af[mf][2], af[mf][3],
                             bf[nf][0], bf[nf][1]);
        }
        __syncthreads();

        if (has_next) {
            #pragma unroll
            for (int i = 0; i < 4; i++) {
                float4 t4 = make_float4(cvt_tf32(aPre[i].x), cvt_tf32(aPre[i].y),
                                        cvt_tf32(aPre[i].z), cvt_tf32(aPre[i].w));
                *(float4*)(sA + rowA[i] * SA + cgA[i]) = t4;
            }
            asm volatile("cp.async.wait_group 0;");
            __syncthreads();
        }
    }

    // ---- epilogue: e[t] = sum_a v[a] * tanh(q[a] + S[t,a]) ----
    float part[4][2];
    #pragma unroll
    for (int mf = 0; mf < 4; mf++) { part[mf][0] = 0.f; part[mf][1] = 0.f; }

    #pragma unroll
    for (int nf = 0; nf < 4; nf++) {
        int c0 = warp_n * 32 + nf * 8 + 2 * (lane & 3);
        float qv0 = g_q[b * A + c0],     qv1 = g_q[b * A + c0 + 1];
        float vv0 = v[c0],               vv1 = v[c0 + 1];
        #pragma unroll
        for (int mf = 0; mf < 4; mf++) {
            part[mf][0] += vv0 * tanhf(qv0 + acc[mf][nf][0])
                         + vv1 * tanhf(qv1 + acc[mf][nf][1]);
            part[mf][1] += vv0 * tanhf(qv0 + acc[mf][nf][2])
                         + vv1 * tanhf(qv1 + acc[mf][nf][3]);
        }
    }

    __syncthreads();
    float* red = dsm;                // reuse: [128][5]
    #pragma unroll
    for (int mf = 0; mf < 4; mf++) {
        #pragma unroll
        for (int r = 0; r < 2; r++) {
            float p = part[mf][r];
            p += __shfl_xor_sync(0xFFFFFFFFu, p, 1);
            p += __shfl_xor_sync(0xFFFFFFFFu, p, 2);
            if ((lane & 3) == 0) {
                int row = warp_m * 64 + mf * 16 + (lane >> 2) + r * 8;
                red[row * 5 + warp_n] = p;
            }
        }
    }
    __syncthreads();

    if (tid < TM) {
        float s = red[tid * 5 + 0] + red[tid * 5 + 1]
                + red[tid * 5 + 2] + red[tid * 5 + 3];
        int t = t0 + tid;
        int mode = g_maskmode;
        g_e[b * T + t] = read_mask(mask, b * T + t, mode) ? -INFINITY : s;
    }
}

// ---------------------------------------------------------------------------
// ctx: inline softmax + context partial + last-block final reduce (ticketed)
// ---------------------------------------------------------------------------
__global__ void __launch_bounds__(256)
ctx_kernel(const float* __restrict__ key,
           float* __restrict__ out) {
    int b = blockIdx.y;
    int c = blockIdx.x;             // 0..15, 64 t each
    int tid = threadIdx.x;          // 256
    int e4 = tid & 127, h = tid >> 7;

    __shared__ float sred[256];
    __shared__ float ws[64];
    __shared__ int s_last;

    // ---- softmax normalization over full T ----
    float vals[4];
    float m = -INFINITY;
    #pragma unroll
    for (int i = 0; i < 4; i++) {
        vals[i] = g_e[b * T + tid + i * 256];
        m = fmaxf(m, vals[i]);
    }
    sred[tid] = m; __syncthreads();
    for (int s = 128; s > 0; s >>= 1) {
        if (tid < s) sred[tid] = fmaxf(sred[tid], sred[tid + s]);
        __syncthreads();
    }
    m = sred[0]; __syncthreads();

    float sum = 0.f;
    #pragma unroll
    for (int i = 0; i < 4; i++)
        sum += expf(vals[i] - m);
    sred[tid] = sum; __syncthreads();
    for (int s = 128; s > 0; s >>= 1) {
        if (tid < s) sred[tid] += sred[tid + s];
        __syncthreads();
    }
    float inv = 1.f / sred[0];
    __syncthreads();

    // ---- this block's 64-t weight slice ----
    if (tid < 64) {
        float w = expf(g_e[b * T + c * 64 + tid] - m) * inv;
        ws[tid] = w;
        out[B * E + (size_t)b * T + c * 64 + tid] = w;
    }
    __syncthreads();

    // ---- context partial ----
    const float* w = ws + h * 32;
    const float4* kp = (const float4*)(key + (size_t)b * T * E)
                     + (size_t)(c * 64 + h * 32) * (E / 4) + e4;
    float4 acc = make_float4(0.f, 0.f, 0.f, 0.f);
    #pragma unroll 8
    for (int t = 0; t < 32; t++) {
        float4 k4 = kp[(size_t)t * (E / 4)];
        float wt = w[t];
        acc.x += wt * k4.x; acc.y += wt * k4.y;
        acc.z += wt * k4.z; acc.w += wt * k4.w;
    }
    __shared__ float4 sred4[256];
    sred4[tid] = acc;
    __syncthreads();
    if (h == 0) {
        float4 o = sred4[tid];
        float4 p = sred4[tid + 128];
        o.x += p.x; o.y += p.y; o.z += p.z; o.w += p.w;
        g_ctxpart4[(b * 16 + c) * (E / 4) + e4] = o;
    }
    __threadfence();
    __syncthreads();

    // ---- ticket: last block of this b does the final reduce ----
    if (tid == 0)
        s_last = (atomicAdd(&g_cnt[b], 1) == 15);
    __syncthreads();
    if (s_last) {
        const float* parts = (const float*)g_ctxpart4;
        #pragma unroll 1
        for (int e = tid; e < E; e += 256) {
            float s = 0.f;
            #pragma unroll
            for (int k = 0; k < 16; k++)
                s += parts[(b * 16 + k) * E + e];
            out[(size_t)b * E + e] = s;
        }
    }
}

// ---------------------------------------------------------------------------
extern "C" void kernel_launch(void* const* d_in, const int* in_sizes, int n_in,
                              void* d_out, int out_size) {
    const float* query  = (const float*)d_in[0];
    const float* key    = (const float*)d_in[1];
    const float* cat    = (const float*)d_in[2];
    const void*  mask   = (const void*)d_in[3];
    const float* Wq     = (const float*)d_in[4];
    const float* Wk     = (const float*)d_in[5];
    const float* conv_w = (const float*)d_in[6];
    const float* gamma  = (const float*)d_in[7];
    const float* beta   = (const float*)d_in[8];
    const float* mean   = (const float*)d_in[9];
    const float* var    = (const float*)d_in[10];
    const float* Wloc   = (const float*)d_in[11];
    const float* v      = (const float*)d_in[12];
    float* out = (float*)d_out;

    cudaFuncSetAttribute(energy_kernel,
                         cudaFuncAttributeMaxDynamicSharedMemorySize, SMEM_BYTES);

    prep_kernel<<<NB_PREP, 256>>>(query, Wq, cat, conv_w, gamma, beta, mean, var,
                                  Wk, Wloc, (const unsigned int*)mask);
    energy_kernel<<<dim3(T / TM, B), 256, SMEM_BYTES>>>(key, mask, v);
    ctx_kernel<<<dim3(16, B), 256>>>(key, out);
}

// round 11
// speedup vs baseline: 1.3285x; 1.2564x over previous
#include <cuda_runtime.h>
#include <cuda_fp16.h>
#include <math.h>
#include <stdint.h>

#define B 64
#define T 1024
#define E 512
#define R 1024
#define A 128
#define F 32
#define KS 31
#define PADC 15

#define TM 128          // t-tile of energy GEMM
#define KC 32           // k-chunk
#define NCHUNK 17       // 16 key chunks + 1 feat/Wloc chunk
#define SAH 40          // A smem row stride (halves) -> conflict-free frags
#define SBH 40          // B smem col stride (halves)
#define SZAH (TM * SAH) // 5120 halves = 10240 B
#define SZBH (A * SBH)  // 5120 halves = 10240 B
#define SMEM_BYTES ((SZAH + 2 * SZBH) * 2)   // 30720 B

// prep grid layout (loc reverted to R8 shape)
#define NB_LOC  256     // 4 per batch x 64 (256 t each)
#define NB_QP   64
#define NB_WB   68
#define NB_PREP (NB_LOC + NB_QP + NB_WB + 1)

// scratch (allocation-free rule: __device__ globals)
__device__ float  g_q[B * A];
__device__ __half g_feath[(size_t)B * T * F];        // 4 MB, [B][T][F] half
__device__ float  g_e[B * T];
__device__ float4 g_ctxpart4[B * 16 * E / 4];
__device__ __half g_wbh[(E + F) * A];                // per-chunk [col][k] half
__device__ int    g_maskmode;
__device__ int    g_cnt[B];

// ---------------------------------------------------------------------------
__device__ __forceinline__ void cp16(void* dst_smem, const void* src) {
    uint32_t d = (uint32_t)__cvta_generic_to_shared(dst_smem);
    asm volatile("cp.async.ca.shared.global [%0], [%1], 16;" :: "r"(d), "l"(src));
}
__device__ __forceinline__ void mma_f16(float& c0, float& c1, float& c2, float& c3,
                                        uint32_t a0, uint32_t a1, uint32_t a2, uint32_t a3,
                                        uint32_t b0, uint32_t b1) {
    asm volatile(
        "mma.sync.aligned.m16n8k16.row.col.f32.f16.f16.f32 "
        "{%0,%1,%2,%3}, {%4,%5,%6,%7}, {%8,%9}, {%0,%1,%2,%3};"
        : "+f"(c0), "+f"(c1), "+f"(c2), "+f"(c3)
        : "r"(a0), "r"(a1), "r"(a2), "r"(a3), "r"(b0), "r"(b1));
}
__device__ __forceinline__ bool read_mask(const void* m, int idx, int mode) {
    if (mode == 1) return ((const int*)m)[idx] != 0;
    if (mode == 2) return ((const float*)m)[idx] != 0.f;
    return ((const unsigned char*)m)[idx] != 0;
}
__device__ __forceinline__ uint32_t pack_h2(float a, float b) {
    __half2 h = __floats2half2_rn(a, b);
    return *(uint32_t*)&h;
}

// ---------------------------------------------------------------------------
// PREP: fused loc-conv / qproj / wbT(half) / mask-sniff+counter-reset
// ---------------------------------------------------------------------------
__global__ void __launch_bounds__(256)
prep_kernel(const float* __restrict__ query,
            const float* __restrict__ Wq,
            const float* __restrict__ cat,
            const float* __restrict__ conv_w,
            const float* __restrict__ gamma,
            const float* __restrict__ beta,
            const float* __restrict__ mean,
            const float* __restrict__ var,
            const float* __restrict__ Wk,
            const float* __restrict__ Wloc,
            const unsigned int* __restrict__ maskw) {
    int blk = blockIdx.x;
    int tid = threadIdx.x;

    if (blk < NB_LOC) {
        // ---------------- loc: conv1d -> relu -> BN -> g_feath ----------------
        int b  = blk >> 2;
        int t0 = (blk & 3) * 256;

        __shared__ float xs[2][288];
        __shared__ float cwT[2 * KS * F];
        __shared__ float bnS[F], bnB[F];
        __shared__ float feat[F][257];

        for (int idx = tid; idx < 2 * 286; idx += 256) {
            int ch = idx / 286, p = idx % 286;
            int tt = t0 - PADC + p;
            xs[ch][p] = (tt >= 0 && tt < T)
                      ? cat[(size_t)b * 2 * T + (size_t)ch * T + tt] : 0.f;
        }
        for (int idx = tid; idx < 2 * KS * F; idx += 256) {
            int f = idx & 31;
            int rest = idx >> 5;
            int ch = rest / KS, k = rest % KS;
            cwT[idx] = conv_w[(f * 2 + ch) * KS + k];
        }
        if (tid < F) {
            float s = rsqrtf(var[tid] + 1e-5f) * gamma[tid];
            bnS[tid] = s;
            bnB[tid] = beta[tid] - mean[tid] * s;
        }
        __syncthreads();

        float4 acc[8];
        #pragma unroll
        for (int u = 0; u < 8; u++) acc[u] = make_float4(0.f, 0.f, 0.f, 0.f);

        #pragma unroll 1
        for (int ch = 0; ch < 2; ch++) {
            #pragma unroll 1
            for (int k = 0; k < KS; k++) {
                float xv = xs[ch][tid + k];
                const float4* c4 = (const float4*)(cwT + (ch * KS + k) * F);
                #pragma unroll
                for (int u = 0; u < 8; u++) {
                    float4 c = c4[u];
                    acc[u].x += xv * c.x; acc[u].y += xv * c.y;
                    acc[u].z += xv * c.z; acc[u].w += xv * c.w;
                }
            }
        }
        #pragma unroll
        for (int u = 0; u < 8; u++) {
            int f0 = u * 4;
            feat[f0 + 0][tid] = fmaxf(acc[u].x, 0.f) * bnS[f0 + 0] + bnB[f0 + 0];
            feat[f0 + 1][tid] = fmaxf(acc[u].y, 0.f) * bnS[f0 + 1] + bnB[f0 + 1];
            feat[f0 + 2][tid] = fmaxf(acc[u].z, 0.f) * bnS[f0 + 2] + bnB[f0 + 2];
            feat[f0 + 3][tid] = fmaxf(acc[u].w, 0.f) * bnS[f0 + 3] + bnB[f0 + 3];
        }
        __syncthreads();

        // transpose to [T][F] halves, coalesced uint2 (4 halves) writes
        #pragma unroll
        for (int i = 0; i < 8; i++) {
            int li = tid + i * 256;          // 0..2047 units of 4 halves
            int t = li >> 3, fg = li & 7;
            uint2 o;
            o.x = pack_h2(feat[fg * 4 + 0][t], feat[fg * 4 + 1][t]);
            o.y = pack_h2(feat[fg * 4 + 2][t], feat[fg * 4 + 3][t]);
            *(uint2*)(g_feath + ((size_t)b * T + t0 + t) * F + fg * 4) = o;
        }
    } else if (blk < NB_LOC + NB_QP) {
        // ---------------- qproj ----------------
        int b = blk - NB_LOC;
        int g = tid >> 7, a = tid & 127;
        __shared__ float sred[2][128];
        const float* qb = query + (size_t)b * R + g * 512;
        const float* wp = Wq + (size_t)(g * 512) * A + a;
        float acc = 0.f;
        #pragma unroll 8
        for (int r = 0; r < 512; r++)
            acc += qb[r] * wp[(size_t)r * A];
        sred[g][a] = acc;
        __syncthreads();
        if (g == 0)
            g_q[b * A + a] = sred[0][a] + sred[1][a];
    } else if (blk < NB_LOC + NB_QP + NB_WB) {
        // ------ wbT: Wk ++ Wloc -> half, transposed per chunk [col][k] ------
        int base = (blk - NB_LOC - NB_QP) * 1024;
        #pragma unroll
        for (int i = 0; i < 4; i++) {
            int idx = base + i * 256 + tid;          // linear [kg][a]
            int kg = idx >> 7, a = idx & 127;
            float x = (idx < E * A) ? Wk[idx] : Wloc[idx - E * A];
            int chunk = kg >> 5, kl = kg & 31;
            g_wbh[(size_t)chunk * (KC * A) + a * KC + kl] = __float2half_rn(x);
        }
    } else {
        // ---------------- mask sniff + counter reset ----------------
        __shared__ int s_not_int, s_not_flt;
        if (tid == 0) { s_not_int = 0; s_not_flt = 0; }
        if (tid < B) g_cnt[tid] = 0;
        __syncthreads();
        int not_int = 0, not_flt = 0;
        for (int i = tid; i < (B * T) / 4; i += 256) {
            unsigned int x = maskw[i];
            if (x > 1u) not_int = 1;
            if (x != 0u && x != 0x3F800000u) not_flt = 1;
        }
        if (not_int) atomicOr(&s_not_int, 1);
        if (not_flt) atomicOr(&s_not_flt, 1);
        __syncthreads();
        if (tid == 0)
            g_maskmode = (!s_not_int) ? 1 : ((!s_not_flt) ? 2 : 0);
    }
}

// ---------------------------------------------------------------------------
// energy: fp16 MMA (m16n8k16) 128x128x(512+32)
//   A: register-prefetch + cvt-in-prefetch, B: cp.async 2-stage from g_wbh
// ---------------------------------------------------------------------------
__global__ void __launch_bounds__(256, 2)
energy_kernel(const float* __restrict__ key,
              const void* __restrict__ mask,
              const float* __restrict__ v) {
    int b  = blockIdx.y;
    int t0 = blockIdx.x * TM;
    int tid = threadIdx.x;
    int lane = tid & 31;
    int wid  = tid >> 5;
    int warp_m = wid >> 2;
    int warp_n = wid & 3;

    extern __shared__ char dsmc[];
    __half* sAh = (__half*)dsmc;                         // [128][SAH]
    __half* stB[2] = {(__half*)dsmc + SZAH,
                      (__half*)dsmc + SZAH + SZBH};

    float acc[4][4][4];
    #pragma unroll
    for (int i = 0; i < 4; i++)
        #pragma unroll
        for (int j = 0; j < 4; j++)
            #pragma unroll
            for (int r = 0; r < 4; r++) acc[i][j][r] = 0.f;

    const float*  keyb  = key + (size_t)b * T * E + (size_t)t0 * E;
    const __half* featb = g_feath + ((size_t)b * T + t0) * F;

    // per-thread A-tile slots: 4 units of 4 halves; row = li>>3, cg = li&7
    int rowA[4], cgA[4];
    #pragma unroll
    for (int i = 0; i < 4; i++) {
        int li = tid + i * 256;
        rowA[i] = li >> 3;
        cgA[i]  = (li & 7) * 4;                  // half index within 32-k row
    }

    // ---- prologue: chunk 0 ----
    uint2 hPre[4];
    #pragma unroll
    for (int i = 0; i < 4; i++) {
        float4 a4 = *(const float4*)(keyb + (size_t)rowA[i] * E + cgA[i]);
        hPre[i].x = pack_h2(a4.x, a4.y);
        hPre[i].y = pack_h2(a4.z, a4.w);
    }
    #pragma unroll
    for (int i = 0; i < 2; i++) {
        int u = tid + i * 256;                   // 512 units of 16B
        int col = u >> 2, kg8 = (u & 3) * 8;
        cp16(stB[0] + col * SBH + kg8, g_wbh + col * KC + kg8);
    }
    asm volatile("cp.async.commit_group;");
    #pragma unroll
    for (int i = 0; i < 4; i++)
        *(uint2*)(sAh + rowA[i] * SAH + cgA[i]) = hPre[i];
    asm volatile("cp.async.wait_group 0;");
    __syncthreads();

    for (int c = 0; c < NCHUNK; c++) {
        __half* sB = stB[c & 1];
        bool has_next = (c + 1 < NCHUNK);
        if (has_next) {
            if (c + 1 < 16) {
                int e0 = (c + 1) * KC;
                #pragma unroll
                for (int i = 0; i < 4; i++) {
                    float4 a4 = *(const float4*)(keyb + (size_t)rowA[i] * E + e0 + cgA[i]);
                    hPre[i].x = pack_h2(a4.x, a4.y);
                    hPre[i].y = pack_h2(a4.z, a4.w);
                }
            } else {
                #pragma unroll
                for (int i = 0; i < 4; i++)
                    hPre[i] = *(const uint2*)(featb + (size_t)rowA[i] * F + cgA[i]);
            }
            const __half* wsrc = g_wbh + (size_t)(c + 1) * (KC * A);
            __half* sBn = stB[(c + 1) & 1];
            #pragma unroll
            for (int i = 0; i < 2; i++) {
                int u = tid + i * 256;
                int col = u >> 2, kg8 = (u & 3) * 8;
                cp16(sBn + col * SBH + kg8, wsrc + col * KC + kg8);
            }
            asm volatile("cp.async.commit_group;");
        }

        // ---- 2 k-steps of m16n8k16 ----
        #pragma unroll
        for (int ks = 0; ks < 2; ks++) {
            int kh = ks * 16 + 2 * (lane & 3);   // half index of this lane's pair
            uint32_t af[4][4];
            #pragma unroll
            for (int mf = 0; mf < 4; mf++) {
                int r0 = warp_m * 64 + mf * 16 + (lane >> 2);
                af[mf][0] = *(const uint32_t*)(sAh + r0 * SAH + kh);
                af[mf][1] = *(const uint32_t*)(sAh + (r0 + 8) * SAH + kh);
                af[mf][2] = *(const uint32_t*)(sAh + r0 * SAH + kh + 8);
                af[mf][3] = *(const uint32_t*)(sAh + (r0 + 8) * SAH + kh + 8);
            }
            uint32_t bf[4][2];
            #pragma unroll
            for (int nf = 0; nf < 4; nf++) {
                int col = warp_n * 32 + nf * 8 + (lane >> 2);
                bf[nf][0] = *(const uint32_t*)(sB + col * SBH + kh);
                bf[nf][1] = *(const uint32_t*)(sB + col * SBH + kh + 8);
            }
            #pragma unroll
            for (int mf = 0; mf < 4; mf++)
                #pragma unroll
                for (int nf = 0; nf < 4; nf++)
                    mma_f16(acc[mf][nf][0], acc[mf][nf][1],
                            acc[mf][nf][2], acc[mf][nf][3],
                            af[mf][0], af[mf][1], af[mf][2], af[mf][3],
                            bf[nf][0], bf[nf][1]);
        }
        __syncthreads();

        if (has_next) {
            #pragma unroll
            for (int i = 0; i < 4; i++)
                *(uint2*)(sAh + rowA[i] * SAH + cgA[i]) = hPre[i];
            asm volatile("cp.async.wait_group 0;");
            __syncthreads();
        }
    }

    // ---- epilogue: e[t] = sum_a v[a] * tanh(q[a] + S[t,a]) ----
    float part[4][2];
    #pragma unroll
    for (int mf = 0; mf < 4; mf++) { part[mf][0] = 0.f; part[mf][1] = 0.f; }

    #pragma unroll
    for (int nf = 0; nf < 4; nf++) {
        int c0 = warp_n * 32 + nf * 8 + 2 * (lane & 3);
        float qv0 = g_q[b * A + c0],     qv1 = g_q[b * A + c0 + 1];
        float vv0 = v[c0],               vv1 = v[c0 + 1];
        #pragma unroll
        for (int mf = 0; mf < 4; mf++) {
            part[mf][0] += vv0 * tanhf(qv0 + acc[mf][nf][0])
                         + vv1 * tanhf(qv1 + acc[mf][nf][1]);
            part[mf][1] += vv0 * tanhf(qv0 + acc[mf][nf][2])
                         + vv1 * tanhf(qv1 + acc[mf][nf][3]);
        }
    }

    __syncthreads();
    float* red = (float*)dsmc;               // reuse: [128][5]
    #pragma unroll
    for (int mf = 0; mf < 4; mf++) {
        #pragma unroll
        for (int r = 0; r < 2; r++) {
            float p = part[mf][r];
            p += __shfl_xor_sync(0xFFFFFFFFu, p, 1);
            p += __shfl_xor_sync(0xFFFFFFFFu, p, 2);
            if ((lane & 3) == 0) {
                int row = warp_m * 64 + mf * 16 + (lane >> 2) + r * 8;
                red[row * 5 + warp_n] = p;
            }
        }
    }
    __syncthreads();

    if (tid < TM) {
        float s = red[tid * 5 + 0] + red[tid * 5 + 1]
                + red[tid * 5 + 2] + red[tid * 5 + 3];
        int t = t0 + tid;
        int mode = g_maskmode;
        g_e[b * T + t] = read_mask(mask, b * T + t, mode) ? -INFINITY : s;
    }
}

// ---------------------------------------------------------------------------
// ctx: inline softmax + context partial + last-block final reduce (ticketed)
// ---------------------------------------------------------------------------
__global__ void __launch_bounds__(256)
ctx_kernel(const float* __restrict__ key,
           float* __restrict__ out) {
    int b = blockIdx.y;
    int c = blockIdx.x;             // 0..15, 64 t each
    int tid = threadIdx.x;          // 256
    int e4 = tid & 127, h = tid >> 7;

    __shared__ float sred[256];
    __shared__ float ws[64];
    __shared__ int s_last;

    float vals[4];
    float m = -INFINITY;
    #pragma unroll
    for (int i = 0; i < 4; i++) {
        vals[i] = g_e[b * T + tid + i * 256];
        m = fmaxf(m, vals[i]);
    }
    sred[tid] = m; __syncthreads();
    for (int s = 128; s > 0; s >>= 1) {
        if (tid < s) sred[tid] = fmaxf(sred[tid], sred[tid + s]);
        __syncthreads();
    }
    m = sred[0]; __syncthreads();

    float sum = 0.f;
    #pragma unroll
    for (int i = 0; i < 4; i++)
        sum += expf(vals[i] - m);
    sred[tid] = sum; __syncthreads();
    for (int s = 128; s > 0; s >>= 1) {
        if (tid < s) sred[tid] += sred[tid + s];
        __syncthreads();
    }
    float inv = 1.f / sred[0];
    __syncthreads();

    if (tid < 64) {
        float w = expf(g_e[b * T + c * 64 + tid] - m) * inv;
        ws[tid] = w;
        out[B * E + (size_t)b * T + c * 64 + tid] = w;
    }
    __syncthreads();

    const float* w = ws + h * 32;
    const float4* kp = (const float4*)(key + (size_t)b * T * E)
                     + (size_t)(c * 64 + h * 32) * (E / 4) + e4;
    float4 acc = make_float4(0.f, 0.f, 0.f, 0.f);
    #pragma unroll 8
    for (int t = 0; t < 32; t++) {
        float4 k4 = kp[(size_t)t * (E / 4)];
        float wt = w[t];
        acc.x += wt * k4.x; acc.y += wt * k4.y;
        acc.z += wt * k4.z; acc.w += wt * k4.w;
    }
    __shared__ float4 sred4[256];
    sred4[tid] = acc;
    __syncthreads();
    if (h == 0) {
        float4 o = sred4[tid];
        float4 p = sred4[tid + 128];
        o.x += p.x; o.y += p.y; o.z += p.z; o.w += p.w;
        g_ctxpart4[(b * 16 + c) * (E / 4) + e4] = o;
    }
    __threadfence();
    __syncthreads();

    if (tid == 0)
        s_last = (atomicAdd(&g_cnt[b], 1) == 15);
    __syncthreads();
    if (s_last) {
        const float* parts = (const float*)g_ctxpart4;
        #pragma unroll 1
        for (int e = tid; e < E; e += 256) {
            float s = 0.f;
            #pragma unroll
            for (int k = 0; k < 16; k++)
                s += parts[(b * 16 + k) * E + e];
            out[(size_t)b * E + e] = s;
        }
    }
}

// ---------------------------------------------------------------------------
extern "C" void kernel_launch(void* const* d_in, const int* in_sizes, int n_in,
                              void* d_out, int out_size) {
    const float* query  = (const float*)d_in[0];
    const float* key    = (const float*)d_in[1];
    const float* cat    = (const float*)d_in[2];
    const void*  mask   = (const void*)d_in[3];
    const float* Wq     = (const float*)d_in[4];
    const float* Wk     = (const float*)d_in[5];
    const float* conv_w = (const float*)d_in[6];
    const float* gamma  = (const float*)d_in[7];
    const float* beta   = (const float*)d_in[8];
    const float* mean   = (const float*)d_in[9];
    const float* var    = (const float*)d_in[10];
    const float* Wloc   = (const float*)d_in[11];
    const float* v      = (const float*)d_in[12];
    float* out = (float*)d_out;

    cudaFuncSetAttribute(energy_kernel,
                         cudaFuncAttributeMaxDynamicSharedMemorySize, SMEM_BYTES);

    prep_kernel<<<NB_PREP, 256>>>(query, Wq, cat, conv_w, gamma, beta, mean, var,
                                  Wk, Wloc, (const unsigned int*)mask);
    energy_kernel<<<dim3(T / TM, B), 256, SMEM_BYTES>>>(key, mask, v);
    ctx_kernel<<<dim3(16, B), 256>>>(key, out);
}